// round 6
// baseline (speedup 1.0000x reference)
#include <cuda_runtime.h>

// ArnoldCat ^7, n=1024: out[a,b] <- in[(239a+169b)&1023, (338a+239b)&1023].
//
// Lattice basis: (a,b) = (169k', j'-239k'), source = (169j', k'+239j').
// Tile (m,n): k' = 32m+k (k<32), j' = 64n+j (j<64).
//   Phase 1 (scalar exact gather): row j -> source row 169j'&1023, 96 consecutive
//     floats from 3*((32m+239j')&1023). Element f=3k+c feeds output row k, chan c.
//     Rows j=0..66 (3-row overlap with tile n+1; loaded with __ldg so the
//     duplicate read is an L2 hit for the neighbor — R5's __ldcs here was the bug).
//   Output-ordered SMEM: osm[k*196 + 3*(j-delta_k) + c], delta_k=(-k)&3,
//     kept when 0 <= j-delta_k < 64.
//   Phase 2 (vector scatter): output row a=169k'&1023; window start pixel
//     sp=(ob+delta_k)&1023, ob=(64n-239k')&1023; ob≡k (mod 4) so sp≡0 (mod 4).
//     Window = 192 contiguous smem floats -> 48 LDS.128 + 48 STG.128 per row.

static constexpr unsigned THREADS = 512u;
static constexpr unsigned BLOCKS  = 16u * 32u * 16u;   // batch x m(32) x n(16) = 8192
static constexpr unsigned P       = 196u;              // smem floats per k-row (192+4)

__global__ void __launch_bounds__(THREADS)
arnold_v6_kernel(const float* __restrict__ in, float4* __restrict__ out4) {
    __shared__ float osm[32u * P];                     // 25088 B

    const unsigned id    = blockIdx.x;
    const unsigned n     = id & 15u;
    const unsigned m     = (id >> 4) & 31u;
    const unsigned batch = id >> 9;
    const unsigned lane  = threadIdx.x & 31u;
    const unsigned warp  = threadIdx.x >> 5;           // 0..15

    const float* inb = in + batch * (1024u * 3072u);

    // ---- per-(lane,t) invariants for the output-ordered SMEM scatter ----
    int      sbase[3];
    unsigned dlo[3];
    #pragma unroll
    for (unsigned t = 0; t < 3u; ++t) {
        unsigned f = lane + 32u * t;                   // float within 96-float segment
        unsigned k = f / 3u;                           // output row this float feeds
        unsigned c = f - 3u * k;                       // channel
        unsigned d = (4u - (k & 3u)) & 3u;             // delta_k = (-k)&3
        dlo[t]   = d;
        sbase[t] = (int)(k * P + c) - 3 * (int)d;      // + 3j at store time
    }

    // ---- Phase 1: batched loads of rows j = warp+16r (r<4) and 64+warp (warp<3) ----
    float v[5][3];
    #pragma unroll
    for (unsigned r = 0; r < 5u; ++r) {
        const bool valid = (r < 4u) || (warp < 3u);
        unsigned j  = (r < 4u) ? (warp + 16u * r) : (64u + warp);
        unsigned jp = 64u * n + j;                     // mod-1024 congruent; ok unreduced
        unsigned ry  = (169u * jp) & 1023u;
        unsigned cb3 = ((32u * m + 239u * jp) & 1023u) * 3u;
        const float* rowp = inb + ry * 3072u;
        #pragma unroll
        for (unsigned t = 0; t < 3u; ++t) {
            unsigned o = cb3 + lane + 32u * t;
            if (o >= 3072u) o -= 3072u;                // rare row wrap
            if (valid)
                v[r][t] = (r < 4u) ? __ldcs(rowp + o)  // main rows: stream
                                   : __ldg(rowp + o);  // overlap rows: cache for neighbor
        }
    }
    // ---- scatter into output-ordered SMEM (addr = sbase + 3j) ----
    #pragma unroll
    for (unsigned r = 0; r < 5u; ++r) {
        const bool valid = (r < 4u) || (warp < 3u);
        unsigned j = (r < 4u) ? (warp + 16u * r) : (64u + warp);
        #pragma unroll
        for (unsigned t = 0; t < 3u; ++t) {
            if (valid && (j - dlo[t] < 64u))           // unsigned: also rejects j<delta
                osm[sbase[t] + 3 * (int)j] = v[r][t];
        }
    }
    __syncthreads();

    // ---- Phase 2: 32 output rows, contiguous 48xfloat4 window per row ----
    if (lane < 24u) {
        const float4* osm4 = reinterpret_cast<const float4*>(osm);
        float4* outb = out4 + batch * (1024u * 768u);
        const unsigned d = (4u - (warp & 3u)) & 3u;    // delta_k; k ≡ warp (mod 4)
        #pragma unroll
        for (unsigned it = 0; it < 2u; ++it) {
            unsigned k  = warp + 16u * it;
            unsigned kp = 32u * m + k;
            unsigned a  = (169u * kp) & 1023u;                 // output row
            unsigned ob = (64u * n - 239u * kp) & 1023u;       // pixel for j=0
            unsigned sp = (ob + d) & 1023u;                    // aligned window start
            unsigned wb = (sp >> 2) * 3u;                      // quad base in out row
            float4* orow = outb + a * 768u;
            #pragma unroll
            for (unsigned h = 0; h < 2u; ++h) {
                unsigned q  = lane + 24u * h;                  // 0..47
                unsigned wi = wb + q;
                if (wi >= 768u) wi -= 768u;                    // row wrap
                __stcs(orow + wi, osm4[k * 49u + q]);          // LDS.128 + STG.128
            }
        }
    }
}

extern "C" void kernel_launch(void* const* d_in, const int* in_sizes, int n_in,
                              void* d_out, int out_size) {
    (void)in_sizes; (void)n_in; (void)out_size;
    arnold_v6_kernel<<<BLOCKS, THREADS>>>((const float*)d_in[0], (float4*)d_out);
}

// round 7
// speedup vs baseline: 1.1248x; 1.1248x over previous
#include <cuda_runtime.h>

// ArnoldCat ^7, n=1024: out[a,b] <- in[(239a+169b)&1023, (338a+239b)&1023].
//
// Lattice basis: (a,b) = (169k', j'-239k'), source = (169j', k'+239j').
// Tile (m,n): k'=32m+k, j'=32n+j, k,j in [0,32). Exact partition of both input
// and output rows (no overlap, no duplicate traffic).
//   Phase 1: row j -> source row 169j'&1023, 96 consecutive floats at
//            3*((32m+239j')&1023). Element f=3k+c feeds output row k, chan c.
//            Stored output-ordered: osm[99k + c + 3j].
//   Phase 2: output row a=169k'&1023, 96 consecutive floats at
//            3*((32n-239k')&1023); float f=3j+c read from osm[99k + f].
// Stride 99 ≡ 3 (mod 32) makes both STS and LDS addr ≡ lane + const (mod 32):
// conflict-free. Row wrap tests are warp-uniform -> uniform branch; fast path
// is one row pointer + immediate offsets (no per-element address ALU).

static constexpr unsigned THREADS = 256u;
static constexpr unsigned BLOCKS  = 16u * 32u * 32u;   // batch x m x n
static constexpr unsigned IMG_F   = 1024u * 3072u;

__global__ void __launch_bounds__(THREADS)
arnold_v7_kernel(const float* __restrict__ in, float* __restrict__ out) {
    __shared__ float osm[3168];                        // 32 x 99 floats = 12672 B

    const unsigned id    = blockIdx.x;
    const unsigned n     = id & 31u;
    const unsigned m     = (id >> 5) & 31u;
    const unsigned batch = id >> 10;
    const unsigned lane  = threadIdx.x & 31u;
    const unsigned warp  = threadIdx.x >> 5;           // 0..7

    const float* inb = in + batch * IMG_F;

    // per-(lane,t) invariant: element f = lane+32t -> smem base 99*(f/3) + f%3
    unsigned sb[3];
    #pragma unroll
    for (unsigned t = 0; t < 3u; ++t) {
        unsigned f = lane + 32u * t;
        unsigned k = f / 3u;
        sb[t] = 99u * k + (f - 3u * k);
    }

    // ---- Phase 1: batched exact gather (12 independent LDGs) ----
    float v[4][3];
    #pragma unroll
    for (unsigned r = 0; r < 4u; ++r) {
        unsigned j   = warp + 8u * r;
        unsigned jp  = 32u * n + j;
        unsigned ry  = (169u * jp) & 1023u;
        unsigned cb3 = ((32u * m + 239u * jp) & 1023u) * 3u;
        const float* rowp = inb + ry * 3072u;
        if (cb3 <= 3072u - 96u) {                      // warp-uniform fast path
            const float* seg = rowp + cb3 + lane;
            v[r][0] = __ldcs(seg);
            v[r][1] = __ldcs(seg + 32u);
            v[r][2] = __ldcs(seg + 64u);
        } else {                                       // row wraps (rare)
            #pragma unroll
            for (unsigned t = 0; t < 3u; ++t) {
                unsigned o = cb3 + lane + 32u * t;
                if (o >= 3072u) o -= 3072u;
                v[r][t] = __ldcs(rowp + o);
            }
        }
    }
    #pragma unroll
    for (unsigned r = 0; r < 4u; ++r) {                // conflict-free STS
        unsigned j3 = 3u * (warp + 8u * r);
        #pragma unroll
        for (unsigned t = 0; t < 3u; ++t)
            osm[sb[t] + j3] = v[r][t];
    }
    __syncthreads();

    // ---- Phase 2: exact scatter, contiguous smem rows ----
    float* outb = out + batch * IMG_F;
    #pragma unroll
    for (unsigned it = 0; it < 4u; ++it) {
        unsigned k   = warp + 8u * it;
        unsigned kp  = 32u * m + k;
        unsigned a   = (169u * kp) & 1023u;
        unsigned ob3 = ((32u * n - 239u * kp) & 1023u) * 3u;
        const float* sr = osm + 99u * k + lane;        // base + immediate offsets
        float r0 = sr[0], r1 = sr[32], r2 = sr[64];
        float* orow = outb + a * 3072u;
        if (ob3 <= 3072u - 96u) {                      // warp-uniform fast path
            float* seg = orow + ob3 + lane;
            __stcs(seg,       r0);
            __stcs(seg + 32u, r1);
            __stcs(seg + 64u, r2);
        } else {                                       // row wraps (rare)
            float rr[3] = {r0, r1, r2};
            #pragma unroll
            for (unsigned t = 0; t < 3u; ++t) {
                unsigned o = ob3 + lane + 32u * t;
                if (o >= 3072u) o -= 3072u;
                __stcs(orow + o, rr[t]);
            }
        }
    }
}

extern "C" void kernel_launch(void* const* d_in, const int* in_sizes, int n_in,
                              void* d_out, int out_size) {
    (void)in_sizes; (void)n_in; (void)out_size;
    arnold_v7_kernel<<<BLOCKS, THREADS>>>((const float*)d_in[0], (float*)d_out);
}